// round 14
// baseline (speedup 1.0000x reference)
#include <cuda_runtime.h>
#include <cstdint>

// Problem constants
#define NPTS   65536      // B*S = 4*16384
#define C      64         // IN_C == OUT_C
#define KNB    16         // neighbors
#define PPB    8          // points per block
#define ROWS   128        // PPB*KNB neighbor rows per block
#define AS     68         // padded row stride
#define HS     20         // padded row stride for H buffer
#define THREADS 256

// ---------------- device-global weight scratch (no allocs) ----------------
__device__ __align__(16) float gWv[4096];      // [c][o]
__device__ __align__(16) float gWpe2[4096];    // [c][o]
__device__ __align__(16) float gWa2_t[1024];   // [m][o]
__device__ __align__(16) float gWpe1[192];     // [d][o]
__device__ __align__(16) float gKa1p[1024];    // packed: [(i>>1)*32 + m*2 + (i&1)] = -(Wa1@Wk)[m][i]
__device__ __align__(16) float gPa1p[1024];    // packed:  (Wa1@Wpe2)[m][i]
__device__ __align__(16) float gQa1[1024];     // [i][m] =  (Wa1@Wq)[m][i]

__global__ void prep_kernel(const float* __restrict__ Wq, const float* __restrict__ Wk,
                            const float* __restrict__ Wv, const float* __restrict__ Wpe1,
                            const float* __restrict__ Wpe2, const float* __restrict__ Wa1,
                            const float* __restrict__ Wa2) {
    int t = blockIdx.x * blockDim.x + threadIdx.x;
    if (t < 4096) {
        int o = t >> 6, c = t & 63;          // source row-major [o][c]
        gWv  [c*64 + o] = Wv[t];
        gWpe2[c*64 + o] = Wpe2[t];
    }
    if (t < 1024) {
        int o = t >> 4, m = t & 15;          // Wa2 is [64][16]
        gWa2_t[m*64 + o] = Wa2[t];
    }
    if (t < 192) {
        int o = t / 3, d = t - o*3;          // Wpe1 is [64][3]
        gWpe1[d*64 + o] = Wpe1[t];
    }
    // fold Wa1 into Wk / Wpe2 / Wq (tiny 16x64x64 matmuls), packed k-pair layout
    if (t < 3072) {
        int sel = t >> 10, idx = t & 1023;
        int i = idx >> 4, m = idx & 15;
        const float* M = (sel == 0) ? Wk : (sel == 1) ? Wpe2 : Wq;
        float acc = 0.f;
#pragma unroll 8
        for (int c = 0; c < 64; ++c) acc += Wa1[m*64 + c] * M[c*64 + i];
        int pidx = (i>>1)*32 + m*2 + (i&1);
        if (sel == 0)      gKa1p[pidx] = -acc;   // negated: h += A @ (-Wka1)
        else if (sel == 1) gPa1p[pidx] = acc;
        else               gQa1[i*16 + m] = acc;
    }
}

// ---------------- f32x2 packed math helpers ----------------
__device__ __forceinline__ void fma2(uint64_t& d, uint64_t a, uint64_t b) {
    asm("fma.rn.f32x2 %0, %1, %2, %0;" : "+l"(d) : "l"(a), "l"(b));
}
__device__ __forceinline__ uint64_t pack2(float x, float y) {
    uint64_t d; asm("mov.b64 %0, {%1, %2};" : "=l"(d) : "f"(x), "f"(y)); return d;
}
__device__ __forceinline__ uint64_t dup2(float x) { return pack2(x, x); }
__device__ __forceinline__ void unpack2(uint64_t v, float& x, float& y) {
    asm("mov.b64 {%0, %1}, %2;" : "=f"(x), "=f"(y) : "l"(v));
}
__device__ __forceinline__ uint64_t relu2(uint64_t v) {
    float x, y; unpack2(v, x, y); return pack2(fmaxf(x, 0.f), fmaxf(y, 0.f));
}
__device__ __forceinline__ float hsum2(uint64_t v) {
    float x, y; unpack2(v, x, y); return x + y;
}

// ---------------- main fused kernel ----------------
__global__ void __launch_bounds__(THREADS, 1)
lab_kernel(const float* __restrict__ cxyz, const float* __restrict__ cfeat,
           const float* __restrict__ nxyz, const float* __restrict__ nfeat,
           const float* __restrict__ Wproj, const float* __restrict__ lnw,
           const float* __restrict__ lnb,  float* __restrict__ out) {
    extern __shared__ float sm[];
    float* sNF   = sm;                 // [128][AS] neigh_feat -> later vpe
    float* sPE   = sNF  + 8704;        // [128][AS] pe_raw -> logits
    float* sH    = sPE  + 8704;        // [128][HS] h
    float* sREL  = sH   + 2560;        // [128][4]  relative xyz
    float* sCF   = sREL + 512;         // [8][64]   center_feat
    float* sQ16  = sCF  + 512;         // [8][16]   qa1
    float* sO    = sQ16 + 128;         // [8][64]   attention output
    float* sY    = sO   + 512;         // [8][64]   y (pre-LN)
    float* sWv   = sY   + 512;         // [64][64]  Wv^T
    float* sWpe2 = sWv  + 4096;        // [64][64]  Wpe2^T
    float* sKa1  = sWpe2+ 4096;        // packed 1024
    float* sPa1  = sKa1 + 1024;        // packed 1024
    float* sWa2  = sPa1 + 1024;        // [16][64]
    float* sWpe1 = sWa2 + 1024;        // [3][64]
    // total 33600 floats = 134400 B -> 1 block/SM

    const int tid = threadIdx.x;
    const int p0  = blockIdx.x * PPB;
    const int w   = tid >> 5;          // warp -> 8-col block + 2-mid block
    const int l   = tid & 31;
    const int o0  = w * 8;
    const int m0  = w * 2;
    int r_[4];
#pragma unroll
    for (int j = 0; j < 4; ++j) r_[j] = l + 32*j;   // 4 rows per thread

    // ---- Stage A: load inputs + stage weights into smem ----
    {
        const float4* nf4 = reinterpret_cast<const float4*>(nfeat + (size_t)p0*KNB*C);
#pragma unroll
        for (int j = tid; j < ROWS*C/4; j += THREADS) {
            float4 v = __ldcs(nf4 + j);
            int e = j*4; int r = e >> 6; int c = e & 63;
            *reinterpret_cast<float4*>(sNF + r*AS + c) = v;
        }
#pragma unroll
        for (int j = tid; j < 1024; j += THREADS) {
            reinterpret_cast<float4*>(sWv)[j]   = reinterpret_cast<const float4*>(gWv)[j];
            reinterpret_cast<float4*>(sWpe2)[j] = reinterpret_cast<const float4*>(gWpe2)[j];
        }
        // 768 float4s for Ka1/Pa1/Wa2 -- FIXED: strided loop (was single-pass, left
        // sPa1/sWa2 unwritten with 256 threads -> R13's rel_err 1.1e-2)
#pragma unroll
        for (int j = tid; j < 768; j += THREADS) {
            if (j < 256)      reinterpret_cast<float4*>(sKa1)[j]     = reinterpret_cast<const float4*>(gKa1p)[j];
            else if (j < 512) reinterpret_cast<float4*>(sPa1)[j-256] = reinterpret_cast<const float4*>(gPa1p)[j-256];
            else              reinterpret_cast<float4*>(sWa2)[j-512] = reinterpret_cast<const float4*>(gWa2_t)[j-512];
        }
        if (tid < 48)
            reinterpret_cast<float4*>(sWpe1)[tid] = reinterpret_cast<const float4*>(gWpe1)[tid];
        if (tid < PPB*C/4) {
            float4 v = __ldcs(reinterpret_cast<const float4*>(cfeat + (size_t)p0*C) + tid);
            int e = tid*4; int i = e >> 6; int c = e & 63;
            *reinterpret_cast<float4*>(sCF + i*C + c) = v;
        }
        if (tid < ROWS) {
            int r = tid, i = r >> 4;
            float cx0 = __ldcs(cxyz + (p0+i)*3 + 0);
            float cx1 = __ldcs(cxyz + (p0+i)*3 + 1);
            float cx2 = __ldcs(cxyz + (p0+i)*3 + 2);
            int nb = (p0*KNB + r)*3;
            sREL[r*4+0] = __ldcs(nxyz + nb + 0) - cx0;
            sREL[r*4+1] = __ldcs(nxyz + nb + 1) - cx1;
            sREL[r*4+2] = __ldcs(nxyz + nb + 2) - cx2;
        }
    }
    __syncthreads();

    // ---- qa1 = cf @ (Wa1 Wq)^T -> sQ16 (8 points x 16 mids) ----
    if (tid < 128) {
        int p = tid >> 4, m = tid & 15;
        float acc = 0.f;
#pragma unroll 8
        for (int c = 0; c < 64; ++c) acc = fmaf(sCF[p*C + c], __ldg(gQa1 + c*16 + m), acc);
        sQ16[p*16 + m] = acc;
    }

    // ---- Stage B: pe_raw = relu(rel @ Wpe1^T) -> sPE (4 rows x 8 cols) ----
    {
        uint64_t b[4][4];
#pragma unroll
        for (int r = 0; r < 4; ++r)
#pragma unroll
            for (int j = 0; j < 4; ++j) b[r][j] = 0ULL;
#pragma unroll
        for (int d = 0; d < 3; ++d) {
            const float* wr = sWpe1 + d*64 + o0;
            ulonglong2 w01 = *reinterpret_cast<const ulonglong2*>(wr);
            ulonglong2 w23 = *reinterpret_cast<const ulonglong2*>(wr + 4);
#pragma unroll
            for (int r = 0; r < 4; ++r) {
                uint64_t a = dup2(sREL[r_[r]*4 + d]);
                fma2(b[r][0], a, w01.x); fma2(b[r][1], a, w01.y);
                fma2(b[r][2], a, w23.x); fma2(b[r][3], a, w23.y);
            }
        }
#pragma unroll
        for (int r = 0; r < 4; ++r) {
            *reinterpret_cast<ulonglong2*>(sPE + r_[r]*AS + o0)     = make_ulonglong2(relu2(b[r][0]), relu2(b[r][1]));
            *reinterpret_cast<ulonglong2*>(sPE + r_[r]*AS + o0 + 4) = make_ulonglong2(relu2(b[r][2]), relu2(b[r][3]));
        }
    }
    __syncthreads();   // (1) pe_raw + qa1 visible

    // ---- Stage C: pe = pe_raw @ Wpe2^T (regs) ; hpe = pe_raw @ Pa1 (k-pair packed) ----
    uint64_t pc[4][4];
    uint64_t hpe[4][2];
    {
#pragma unroll
        for (int r = 0; r < 4; ++r) {
            pc[r][0]=pc[r][1]=pc[r][2]=pc[r][3]=0ULL;
            hpe[r][0]=hpe[r][1]=0ULL;
        }
#pragma unroll 2
        for (int c = 0; c < 64; c += 4) {
            float4 A[4];
#pragma unroll
            for (int r = 0; r < 4; ++r)
                A[r] = *reinterpret_cast<const float4*>(sPE + r_[r]*AS + c);
            // mids (k-pair packed: 2 loads per chunk)
            ulonglong2 P0 = *reinterpret_cast<const ulonglong2*>(sPa1 + (c>>1)*32 + m0*2);
            ulonglong2 P1 = *reinterpret_cast<const ulonglong2*>(sPa1 + (c>>1)*32 + 32 + m0*2);
#pragma unroll
            for (int r = 0; r < 4; ++r) {
                uint64_t Ap0 = pack2(A[r].x, A[r].y);
                uint64_t Ap1 = pack2(A[r].z, A[r].w);
                fma2(hpe[r][0], Ap0, P0.x); fma2(hpe[r][1], Ap0, P0.y);
                fma2(hpe[r][0], Ap1, P1.x); fma2(hpe[r][1], Ap1, P1.y);
            }
            float Av[4][4];
#pragma unroll
            for (int r = 0; r < 4; ++r) { Av[r][0]=A[r].x; Av[r][1]=A[r].y; Av[r][2]=A[r].z; Av[r][3]=A[r].w; }
#pragma unroll
            for (int u = 0; u < 4; ++u) {
                const float* wr = sWpe2 + (c+u)*64 + o0;
                ulonglong2 w01 = *reinterpret_cast<const ulonglong2*>(wr);
                ulonglong2 w23 = *reinterpret_cast<const ulonglong2*>(wr + 4);
#pragma unroll
                for (int r = 0; r < 4; ++r) {
                    uint64_t a = dup2(Av[r][u]);
                    fma2(pc[r][0], a, w01.x); fma2(pc[r][1], a, w01.y);
                    fma2(pc[r][2], a, w23.x); fma2(pc[r][3], a, w23.y);
                }
            }
        }
    }

    // ---- Stage D: v = A@Wv^T ; hk = A@(-Wka1) (k-pair) ; vpe -> sNF ; h -> sH ----
    {
        uint64_t av[4][4];
        uint64_t hk[4][2];
#pragma unroll
        for (int r = 0; r < 4; ++r) {
            av[r][0]=pc[r][0]; av[r][1]=pc[r][1]; av[r][2]=pc[r][2]; av[r][3]=pc[r][3];
            hk[r][0]=hpe[r][0]; hk[r][1]=hpe[r][1];
        }
#pragma unroll 2
        for (int c = 0; c < 64; c += 4) {
            float4 A[4];
#pragma unroll
            for (int r = 0; r < 4; ++r)
                A[r] = *reinterpret_cast<const float4*>(sNF + r_[r]*AS + c);
            ulonglong2 K0 = *reinterpret_cast<const ulonglong2*>(sKa1 + (c>>1)*32 + m0*2);
            ulonglong2 K1 = *reinterpret_cast<const ulonglong2*>(sKa1 + (c>>1)*32 + 32 + m0*2);
#pragma unroll
            for (int r = 0; r < 4; ++r) {
                uint64_t Ap0 = pack2(A[r].x, A[r].y);
                uint64_t Ap1 = pack2(A[r].z, A[r].w);
                fma2(hk[r][0], Ap0, K0.x); fma2(hk[r][1], Ap0, K0.y);
                fma2(hk[r][0], Ap1, K1.x); fma2(hk[r][1], Ap1, K1.y);
            }
            float Av[4][4];
#pragma unroll
            for (int r = 0; r < 4; ++r) { Av[r][0]=A[r].x; Av[r][1]=A[r].y; Av[r][2]=A[r].z; Av[r][3]=A[r].w; }
#pragma unroll
            for (int u = 0; u < 4; ++u) {
                const float* wr = sWv + (c+u)*64 + o0;
                ulonglong2 w01 = *reinterpret_cast<const ulonglong2*>(wr);
                ulonglong2 w23 = *reinterpret_cast<const ulonglong2*>(wr + 4);
#pragma unroll
                for (int r = 0; r < 4; ++r) {
                    uint64_t a = dup2(Av[r][u]);
                    fma2(av[r][0], a, w01.x); fma2(av[r][1], a, w01.y);
                    fma2(av[r][2], a, w23.x); fma2(av[r][3], a, w23.y);
                }
            }
        }
        __syncthreads();   // (2) all reads of sNF (neigh_feat) and sPE (pe_raw) done
#pragma unroll
        for (int r = 0; r < 4; ++r) {
            *reinterpret_cast<ulonglong2*>(sNF + r_[r]*AS + o0)     = make_ulonglong2(av[r][0], av[r][1]);
            *reinterpret_cast<ulonglong2*>(sNF + r_[r]*AS + o0 + 4) = make_ulonglong2(av[r][2], av[r][3]);
            int p = r_[r] >> 4;
            float q0, q1;
            unpack2(*reinterpret_cast<const uint64_t*>(sQ16 + p*16 + m0), q0, q1);
            float h0 = fmaxf(q0 + hsum2(hk[r][0]), 0.f);
            float h1 = fmaxf(q1 + hsum2(hk[r][1]), 0.f);
            *reinterpret_cast<uint64_t*>(sH + r_[r]*HS + m0) = pack2(h0, h1);
        }
    }
    __syncthreads();   // (3) vpe and h visible

    // ---- Stage G: logits = h @ Wa2^T -> sPE ----
    {
        uint64_t g[4][4];
#pragma unroll
        for (int r = 0; r < 4; ++r) { g[r][0]=g[r][1]=g[r][2]=g[r][3]=0ULL; }
#pragma unroll
        for (int m = 0; m < 16; m += 4) {
            float4 H[4];
#pragma unroll
            for (int r = 0; r < 4; ++r)
                H[r] = *reinterpret_cast<const float4*>(sH + r_[r]*HS + m);
            float Hv[4][4];
#pragma unroll
            for (int r = 0; r < 4; ++r) { Hv[r][0]=H[r].x; Hv[r][1]=H[r].y; Hv[r][2]=H[r].z; Hv[r][3]=H[r].w; }
#pragma unroll
            for (int u = 0; u < 4; ++u) {
                const float* wr = sWa2 + (m+u)*64 + o0;
                ulonglong2 w01 = *reinterpret_cast<const ulonglong2*>(wr);
                ulonglong2 w23 = *reinterpret_cast<const ulonglong2*>(wr + 4);
#pragma unroll
                for (int r = 0; r < 4; ++r) {
                    uint64_t a = dup2(Hv[r][u]);
                    fma2(g[r][0], a, w01.x); fma2(g[r][1], a, w01.y);
                    fma2(g[r][2], a, w23.x); fma2(g[r][3], a, w23.y);
                }
            }
        }
#pragma unroll
        for (int r = 0; r < 4; ++r) {
            *reinterpret_cast<ulonglong2*>(sPE + r_[r]*AS + o0)     = make_ulonglong2(g[r][0], g[r][1]);
            *reinterpret_cast<ulonglong2*>(sPE + r_[r]*AS + o0 + 4) = make_ulonglong2(g[r][2], g[r][3]);
        }
    }
    __syncthreads();   // (4) logits visible

    // ---- Stage H: softmax over K + weighted sum of vpe -> sO (2 points/thread) ----
    {
        int i0 = tid >> 6, o = tid & 63;
#pragma unroll
        for (int half = 0; half < 2; ++half) {
            int p = i0 + half*4;
            int rbase = p * KNB;
            float wv[KNB];
            float mx = -1e30f;
#pragma unroll
            for (int k = 0; k < KNB; ++k) {
                wv[k] = sPE[(rbase+k)*AS + o];
                mx = fmaxf(mx, wv[k]);
            }
            float sum = 0.f;
#pragma unroll
            for (int k = 0; k < KNB; ++k) { wv[k] = __expf(wv[k] - mx); sum += wv[k]; }
            float inv = 1.f / sum;
            float acc = 0.f;
#pragma unroll
            for (int k = 0; k < KNB; ++k) acc = fmaf(wv[k], sNF[(rbase+k)*AS + o], acc);
            sO[p*C + o] = acc * inv;
        }
    }
    __syncthreads();

    // ---- Stage I: proj + residual -> sY (row-cached; Wproj row-major direct) ----
    {
        int i0 = tid >> 6, o = tid & 63;
        int pA = i0, pB = i0 + 4;
        float acc0 = sCF[pA*C + o];
        float acc1 = sCF[pB*C + o];
        const float4* wrow = reinterpret_cast<const float4*>(Wproj + o*64);
#pragma unroll
        for (int h = 0; h < 16; ++h) {
            float4 wv = __ldg(wrow + h);
            float4 a0 = *reinterpret_cast<const float4*>(sO + pA*C + h*4);
            float4 a1 = *reinterpret_cast<const float4*>(sO + pB*C + h*4);
            acc0 = fmaf(a0.x, wv.x, acc0); acc0 = fmaf(a0.y, wv.y, acc0);
            acc0 = fmaf(a0.z, wv.z, acc0); acc0 = fmaf(a0.w, wv.w, acc0);
            acc1 = fmaf(a1.x, wv.x, acc1); acc1 = fmaf(a1.y, wv.y, acc1);
            acc1 = fmaf(a1.z, wv.z, acc1); acc1 = fmaf(a1.w, wv.w, acc1);
        }
        sY[pA*C + o] = acc0;
        sY[pB*C + o] = acc1;
    }
    __syncthreads();

    // ---- Stage J: LayerNorm (warp wp -> point wp) + global store ----
    {
        int wp = tid >> 5, lid = tid & 31;
        float y0 = sY[wp*C + lid];
        float y1 = sY[wp*C + lid + 32];
        float s  = y0 + y1;
        float s2 = y0*y0 + y1*y1;
#pragma unroll
        for (int off = 16; off; off >>= 1) {
            s  += __shfl_xor_sync(0xFFFFFFFFu, s,  off);
            s2 += __shfl_xor_sync(0xFFFFFFFFu, s2, off);
        }
        float mu  = s * (1.f/64.f);
        float var = s2 * (1.f/64.f) - mu*mu;
        float rs  = rsqrtf(var + 1e-5f);
        int g = p0 + wp;
        out[(size_t)g*C + lid]      = (y0 - mu) * rs * lnw[lid]      + lnb[lid];
        out[(size_t)g*C + lid + 32] = (y1 - mu) * rs * lnw[lid + 32] + lnb[lid + 32];
    }
}

// ---------------- launch ----------------
extern "C" void kernel_launch(void* const* d_in, const int* in_sizes, int n_in,
                              void* d_out, int out_size) {
    (void)in_sizes; (void)n_in; (void)out_size;
    const float* cxyz  = (const float*)d_in[0];
    const float* cfeat = (const float*)d_in[1];
    const float* nxyz  = (const float*)d_in[2];
    const float* nfeat = (const float*)d_in[3];
    const float* Wq    = (const float*)d_in[4];
    const float* Wk    = (const float*)d_in[5];
    const float* Wv    = (const float*)d_in[6];
    const float* Wpe1  = (const float*)d_in[7];
    const float* Wpe2  = (const float*)d_in[8];
    const float* Wa1   = (const float*)d_in[9];
    const float* Wa2   = (const float*)d_in[10];
    const float* Wproj = (const float*)d_in[11];
    const float* lnw   = (const float*)d_in[12];
    const float* lnb   = (const float*)d_in[13];

    prep_kernel<<<16, 256>>>(Wq, Wk, Wv, Wpe1, Wpe2, Wa1, Wa2);

    size_t smem = 33600 * sizeof(float);   // 134400 B -> 1 block/SM
    cudaFuncSetAttribute(lab_kernel, cudaFuncAttributeMaxDynamicSharedMemorySize, (int)smem);
    lab_kernel<<<NPTS/PPB, THREADS, smem>>>(cxyz, cfeat, nxyz, nfeat, Wproj, lnw, lnb, (float*)d_out);
}

// round 16
// speedup vs baseline: 1.0922x; 1.0922x over previous
#include <cuda_runtime.h>
#include <cstdint>

// Problem constants
#define NPTS   65536      // B*S = 4*16384
#define C      64         // IN_C == OUT_C
#define KNB    16         // neighbors
#define PPB    8          // points per block
#define ROWS   128        // PPB*KNB neighbor rows per block
#define AS     68         // padded row stride
#define HS     20         // padded row stride for H buffer
#define THREADS 256

// ---------------- device-global weight scratch (no allocs) ----------------
__device__ __align__(16) float gWv[4096];      // [c][o]
__device__ __align__(16) float gWpe2[4096];    // [c][o]
__device__ __align__(16) float gWa2_t[1024];   // [m][o]
__device__ __align__(16) float gWpe1[192];     // [d][o]
__device__ __align__(16) float gKa1p[1024];    // packed: [(i>>1)*32 + m*2 + (i&1)] = -(Wa1@Wk)[m][i]
__device__ __align__(16) float gPa1p[1024];    // packed:  (Wa1@Wpe2)[m][i]
__device__ __align__(16) float gQa1[1024];     // [i][m] =  (Wa1@Wq)[m][i]

__global__ void prep_kernel(const float* __restrict__ Wq, const float* __restrict__ Wk,
                            const float* __restrict__ Wv, const float* __restrict__ Wpe1,
                            const float* __restrict__ Wpe2, const float* __restrict__ Wa1,
                            const float* __restrict__ Wa2) {
    int t = blockIdx.x * blockDim.x + threadIdx.x;
    if (t < 4096) {
        int o = t >> 6, c = t & 63;          // source row-major [o][c]
        gWv  [c*64 + o] = Wv[t];
        gWpe2[c*64 + o] = Wpe2[t];
    }
    if (t < 1024) {
        int o = t >> 4, m = t & 15;          // Wa2 is [64][16]
        gWa2_t[m*64 + o] = Wa2[t];
    }
    if (t < 192) {
        int o = t / 3, d = t - o*3;          // Wpe1 is [64][3]
        gWpe1[d*64 + o] = Wpe1[t];
    }
    // fold Wa1 into Wk / Wpe2 / Wq (tiny 16x64x64 matmuls), packed k-pair layout
    if (t < 3072) {
        int sel = t >> 10, idx = t & 1023;
        int i = idx >> 4, m = idx & 15;
        const float* M = (sel == 0) ? Wk : (sel == 1) ? Wpe2 : Wq;
        float acc = 0.f;
#pragma unroll 8
        for (int c = 0; c < 64; ++c) acc += Wa1[m*64 + c] * M[c*64 + i];
        int pidx = (i>>1)*32 + m*2 + (i&1);
        if (sel == 0)      gKa1p[pidx] = -acc;   // negated: h += A @ (-Wka1)
        else if (sel == 1) gPa1p[pidx] = acc;
        else               gQa1[i*16 + m] = acc;
    }
}

// ---------------- f32x2 packed math helpers ----------------
__device__ __forceinline__ void fma2(uint64_t& d, uint64_t a, uint64_t b) {
    asm("fma.rn.f32x2 %0, %1, %2, %0;" : "+l"(d) : "l"(a), "l"(b));
}
__device__ __forceinline__ uint64_t pack2(float x, float y) {
    uint64_t d; asm("mov.b64 %0, {%1, %2};" : "=l"(d) : "f"(x), "f"(y)); return d;
}
__device__ __forceinline__ uint64_t dup2(float x) { return pack2(x, x); }
__device__ __forceinline__ void unpack2(uint64_t v, float& x, float& y) {
    asm("mov.b64 {%0, %1}, %2;" : "=f"(x), "=f"(y) : "l"(v));
}
__device__ __forceinline__ uint64_t relu2(uint64_t v) {
    float x, y; unpack2(v, x, y); return pack2(fmaxf(x, 0.f), fmaxf(y, 0.f));
}
__device__ __forceinline__ float hsum2(uint64_t v) {
    float x, y; unpack2(v, x, y); return x + y;
}
// warp-uniform 16B global load (1 L1TEX wavefront, L1-resident weights)
__device__ __forceinline__ ulonglong2 ldg2(const float* p) {
    return __ldg(reinterpret_cast<const ulonglong2*>(p));
}

// ---------------- main fused kernel ----------------
__global__ void __launch_bounds__(THREADS, 2)
lab_kernel(const float* __restrict__ cxyz, const float* __restrict__ cfeat,
           const float* __restrict__ nxyz, const float* __restrict__ nfeat,
           const float* __restrict__ Wproj, const float* __restrict__ lnw,
           const float* __restrict__ lnb,  float* __restrict__ out) {
    extern __shared__ float sm[];
    float* sNF   = sm;                 // [128][AS] neigh_feat -> later vpe
    float* sPE   = sNF  + 8704;        // [128][AS] pe_raw -> logits
    float* sH    = sPE  + 8704;        // [128][HS] h
    float* sREL  = sH   + 2560;        // [128][4]  relative xyz
    float* sCF   = sREL + 512;         // [8][64]   center_feat
    float* sQ16  = sCF  + 512;         // [8][16]   qa1
    float* sO    = sQ16 + 128;         // [8][64]   attention output
    float* sY    = sO   + 512;         // [8][64]   y (pre-LN)
    float* sKa1  = sY   + 512;         // packed 1024
    float* sPa1  = sKa1 + 1024;        // packed 1024
    float* sWa2  = sPa1 + 1024;        // [16][64]
    float* sWpe1 = sWa2 + 1024;        // [3][64]
    // total 25408 floats = 101632 B -> 2 blocks/SM

    const int tid = threadIdx.x;
    const int p0  = blockIdx.x * PPB;
    const int w   = tid >> 5;          // warp -> 8-col block + 2-mid block
    const int l   = tid & 31;
    const int o0  = w * 8;
    const int m0  = w * 2;
    int r_[4];
#pragma unroll
    for (int j = 0; j < 4; ++j) r_[j] = l + 32*j;   // 4 rows per thread

    // ---- Stage A: load inputs + stage small weights into smem ----
    {
        const float4* nf4 = reinterpret_cast<const float4*>(nfeat + (size_t)p0*KNB*C);
#pragma unroll
        for (int j = tid; j < ROWS*C/4; j += THREADS) {
            float4 v = __ldcs(nf4 + j);
            int e = j*4; int r = e >> 6; int c = e & 63;
            *reinterpret_cast<float4*>(sNF + r*AS + c) = v;
        }
        // 768 float4s for Ka1/Pa1/Wa2 (strided: 256 threads need 3 passes)
#pragma unroll
        for (int j = tid; j < 768; j += THREADS) {
            if (j < 256)      reinterpret_cast<float4*>(sKa1)[j]     = reinterpret_cast<const float4*>(gKa1p)[j];
            else if (j < 512) reinterpret_cast<float4*>(sPa1)[j-256] = reinterpret_cast<const float4*>(gPa1p)[j-256];
            else              reinterpret_cast<float4*>(sWa2)[j-512] = reinterpret_cast<const float4*>(gWa2_t)[j-512];
        }
        if (tid < 48)
            reinterpret_cast<float4*>(sWpe1)[tid] = reinterpret_cast<const float4*>(gWpe1)[tid];
        if (tid < PPB*C/4) {
            float4 v = __ldcs(reinterpret_cast<const float4*>(cfeat + (size_t)p0*C) + tid);
            int e = tid*4; int i = e >> 6; int c = e & 63;
            *reinterpret_cast<float4*>(sCF + i*C + c) = v;
        }
        if (tid < ROWS) {
            int r = tid, i = r >> 4;
            float cx0 = __ldcs(cxyz + (p0+i)*3 + 0);
            float cx1 = __ldcs(cxyz + (p0+i)*3 + 1);
            float cx2 = __ldcs(cxyz + (p0+i)*3 + 2);
            int nb = (p0*KNB + r)*3;
            sREL[r*4+0] = __ldcs(nxyz + nb + 0) - cx0;
            sREL[r*4+1] = __ldcs(nxyz + nb + 1) - cx1;
            sREL[r*4+2] = __ldcs(nxyz + nb + 2) - cx2;
        }
    }
    __syncthreads();

    // ---- qa1 = cf @ (Wa1 Wq)^T -> sQ16 (8 points x 16 mids) ----
    if (tid < 128) {
        int p = tid >> 4, m = tid & 15;
        float acc = 0.f;
#pragma unroll 8
        for (int c = 0; c < 64; ++c) acc = fmaf(sCF[p*C + c], __ldg(gQa1 + c*16 + m), acc);
        sQ16[p*16 + m] = acc;
    }

    // ---- Stage B: pe_raw = relu(rel @ Wpe1^T) -> sPE (4 rows x 8 cols) ----
    {
        uint64_t b[4][4];
#pragma unroll
        for (int r = 0; r < 4; ++r)
#pragma unroll
            for (int j = 0; j < 4; ++j) b[r][j] = 0ULL;
#pragma unroll
        for (int d = 0; d < 3; ++d) {
            const float* wr = sWpe1 + d*64 + o0;
            ulonglong2 w01 = *reinterpret_cast<const ulonglong2*>(wr);
            ulonglong2 w23 = *reinterpret_cast<const ulonglong2*>(wr + 4);
#pragma unroll
            for (int r = 0; r < 4; ++r) {
                uint64_t a = dup2(sREL[r_[r]*4 + d]);
                fma2(b[r][0], a, w01.x); fma2(b[r][1], a, w01.y);
                fma2(b[r][2], a, w23.x); fma2(b[r][3], a, w23.y);
            }
        }
#pragma unroll
        for (int r = 0; r < 4; ++r) {
            *reinterpret_cast<ulonglong2*>(sPE + r_[r]*AS + o0)     = make_ulonglong2(relu2(b[r][0]), relu2(b[r][1]));
            *reinterpret_cast<ulonglong2*>(sPE + r_[r]*AS + o0 + 4) = make_ulonglong2(relu2(b[r][2]), relu2(b[r][3]));
        }
    }
    __syncthreads();   // (1) pe_raw + qa1 visible

    // ---- Stage C: pe = pe_raw @ Wpe2^T (regs) ; hpe = pe_raw @ Pa1 (k-pair packed) ----
    uint64_t pc[4][4];
    uint64_t hpe[4][2];
    {
#pragma unroll
        for (int r = 0; r < 4; ++r) {
            pc[r][0]=pc[r][1]=pc[r][2]=pc[r][3]=0ULL;
            hpe[r][0]=hpe[r][1]=0ULL;
        }
#pragma unroll 2
        for (int c = 0; c < 64; c += 4) {
            float4 A[4];
#pragma unroll
            for (int r = 0; r < 4; ++r)
                A[r] = *reinterpret_cast<const float4*>(sPE + r_[r]*AS + c);
            // mids (k-pair packed: 2 loads per chunk)
            ulonglong2 P0 = *reinterpret_cast<const ulonglong2*>(sPa1 + (c>>1)*32 + m0*2);
            ulonglong2 P1 = *reinterpret_cast<const ulonglong2*>(sPa1 + (c>>1)*32 + 32 + m0*2);
#pragma unroll
            for (int r = 0; r < 4; ++r) {
                uint64_t Ap0 = pack2(A[r].x, A[r].y);
                uint64_t Ap1 = pack2(A[r].z, A[r].w);
                fma2(hpe[r][0], Ap0, P0.x); fma2(hpe[r][1], Ap0, P0.y);
                fma2(hpe[r][0], Ap1, P1.x); fma2(hpe[r][1], Ap1, P1.y);
            }
            float Av[4][4];
#pragma unroll
            for (int r = 0; r < 4; ++r) { Av[r][0]=A[r].x; Av[r][1]=A[r].y; Av[r][2]=A[r].z; Av[r][3]=A[r].w; }
#pragma unroll
            for (int u = 0; u < 4; ++u) {
                const float* wr = gWpe2 + (c+u)*64 + o0;   // warp-uniform LDG (L1-resident)
                ulonglong2 w01 = ldg2(wr);
                ulonglong2 w23 = ldg2(wr + 4);
#pragma unroll
                for (int r = 0; r < 4; ++r) {
                    uint64_t a = dup2(Av[r][u]);
                    fma2(pc[r][0], a, w01.x); fma2(pc[r][1], a, w01.y);
                    fma2(pc[r][2], a, w23.x); fma2(pc[r][3], a, w23.y);
                }
            }
        }
    }

    // ---- Stage D: v = A@Wv^T ; hk = A@(-Wka1) (k-pair) ; vpe -> sNF ; h -> sH ----
    {
        uint64_t av[4][4];
        uint64_t hk[4][2];
#pragma unroll
        for (int r = 0; r < 4; ++r) {
            av[r][0]=pc[r][0]; av[r][1]=pc[r][1]; av[r][2]=pc[r][2]; av[r][3]=pc[r][3];
            hk[r][0]=hpe[r][0]; hk[r][1]=hpe[r][1];
        }
#pragma unroll 2
        for (int c = 0; c < 64; c += 4) {
            float4 A[4];
#pragma unroll
            for (int r = 0; r < 4; ++r)
                A[r] = *reinterpret_cast<const float4*>(sNF + r_[r]*AS + c);
            ulonglong2 K0 = *reinterpret_cast<const ulonglong2*>(sKa1 + (c>>1)*32 + m0*2);
            ulonglong2 K1 = *reinterpret_cast<const ulonglong2*>(sKa1 + (c>>1)*32 + 32 + m0*2);
#pragma unroll
            for (int r = 0; r < 4; ++r) {
                uint64_t Ap0 = pack2(A[r].x, A[r].y);
                uint64_t Ap1 = pack2(A[r].z, A[r].w);
                fma2(hk[r][0], Ap0, K0.x); fma2(hk[r][1], Ap0, K0.y);
                fma2(hk[r][0], Ap1, K1.x); fma2(hk[r][1], Ap1, K1.y);
            }
            float Av[4][4];
#pragma unroll
            for (int r = 0; r < 4; ++r) { Av[r][0]=A[r].x; Av[r][1]=A[r].y; Av[r][2]=A[r].z; Av[r][3]=A[r].w; }
#pragma unroll
            for (int u = 0; u < 4; ++u) {
                const float* wr = gWv + (c+u)*64 + o0;     // warp-uniform LDG (L1-resident)
                ulonglong2 w01 = ldg2(wr);
                ulonglong2 w23 = ldg2(wr + 4);
#pragma unroll
                for (int r = 0; r < 4; ++r) {
                    uint64_t a = dup2(Av[r][u]);
                    fma2(av[r][0], a, w01.x); fma2(av[r][1], a, w01.y);
                    fma2(av[r][2], a, w23.x); fma2(av[r][3], a, w23.y);
                }
            }
        }
        __syncthreads();   // (2) all reads of sNF (neigh_feat) and sPE (pe_raw) done
#pragma unroll
        for (int r = 0; r < 4; ++r) {
            *reinterpret_cast<ulonglong2*>(sNF + r_[r]*AS + o0)     = make_ulonglong2(av[r][0], av[r][1]);
            *reinterpret_cast<ulonglong2*>(sNF + r_[r]*AS + o0 + 4) = make_ulonglong2(av[r][2], av[r][3]);
            int p = r_[r] >> 4;
            float q0, q1;
            unpack2(*reinterpret_cast<const uint64_t*>(sQ16 + p*16 + m0), q0, q1);
            float h0 = fmaxf(q0 + hsum2(hk[r][0]), 0.f);
            float h1 = fmaxf(q1 + hsum2(hk[r][1]), 0.f);
            *reinterpret_cast<uint64_t*>(sH + r_[r]*HS + m0) = pack2(h0, h1);
        }
    }
    __syncthreads();   // (3) vpe and h visible

    // ---- Stage G: logits = h @ Wa2^T -> sPE ----
    {
        uint64_t g[4][4];
#pragma unroll
        for (int r = 0; r < 4; ++r) { g[r][0]=g[r][1]=g[r][2]=g[r][3]=0ULL; }
#pragma unroll
        for (int m = 0; m < 16; m += 4) {
            float4 H[4];
#pragma unroll
            for (int r = 0; r < 4; ++r)
                H[r] = *reinterpret_cast<const float4*>(sH + r_[r]*HS + m);
            float Hv[4][4];
#pragma unroll
            for (int r = 0; r < 4; ++r) { Hv[r][0]=H[r].x; Hv[r][1]=H[r].y; Hv[r][2]=H[r].z; Hv[r][3]=H[r].w; }
#pragma unroll
            for (int u = 0; u < 4; ++u) {
                const float* wr = sWa2 + (m+u)*64 + o0;
                ulonglong2 w01 = *reinterpret_cast<const ulonglong2*>(wr);
                ulonglong2 w23 = *reinterpret_cast<const ulonglong2*>(wr + 4);
#pragma unroll
                for (int r = 0; r < 4; ++r) {
                    uint64_t a = dup2(Hv[r][u]);
                    fma2(g[r][0], a, w01.x); fma2(g[r][1], a, w01.y);
                    fma2(g[r][2], a, w23.x); fma2(g[r][3], a, w23.y);
                }
            }
        }
#pragma unroll
        for (int r = 0; r < 4; ++r) {
            *reinterpret_cast<ulonglong2*>(sPE + r_[r]*AS + o0)     = make_ulonglong2(g[r][0], g[r][1]);
            *reinterpret_cast<ulonglong2*>(sPE + r_[r]*AS + o0 + 4) = make_ulonglong2(g[r][2], g[r][3]);
        }
    }
    __syncthreads();   // (4) logits visible

    // ---- Stage H: softmax over K + weighted sum of vpe -> sO (2 points/thread) ----
    {
        int i0 = tid >> 6, o = tid & 63;
#pragma unroll
        for (int half = 0; half < 2; ++half) {
            int p = i0 + half*4;
            int rbase = p * KNB;
            float wv[KNB];
            float mx = -1e30f;
#pragma unroll
            for (int k = 0; k < KNB; ++k) {
                wv[k] = sPE[(rbase+k)*AS + o];
                mx = fmaxf(mx, wv[k]);
            }
            float sum = 0.f;
#pragma unroll
            for (int k = 0; k < KNB; ++k) { wv[k] = __expf(wv[k] - mx); sum += wv[k]; }
            float inv = 1.f / sum;
            float acc = 0.f;
#pragma unroll
            for (int k = 0; k < KNB; ++k) acc = fmaf(wv[k], sNF[(rbase+k)*AS + o], acc);
            sO[p*C + o] = acc * inv;
        }
    }
    __syncthreads();

    // ---- Stage I: proj + residual -> sY (row-cached; Wproj row-major direct) ----
    {
        int i0 = tid >> 6, o = tid & 63;
        int pA = i0, pB = i0 + 4;
        float acc0 = sCF[pA*C + o];
        float acc1 = sCF[pB*C + o];
        const float4* wrow = reinterpret_cast<const float4*>(Wproj + o*64);
#pragma unroll
        for (int h = 0; h < 16; ++h) {
            float4 wv = __ldg(wrow + h);
            float4 a0 = *reinterpret_cast<const float4*>(sO + pA*C + h*4);
            float4 a1 = *reinterpret_cast<const float4*>(sO + pB*C + h*4);
            acc0 = fmaf(a0.x, wv.x, acc0); acc0 = fmaf(a0.y, wv.y, acc0);
            acc0 = fmaf(a0.z, wv.z, acc0); acc0 = fmaf(a0.w, wv.w, acc0);
            acc1 = fmaf(a1.x, wv.x, acc1); acc1 = fmaf(a1.y, wv.y, acc1);
            acc1 = fmaf(a1.z, wv.z, acc1); acc1 = fmaf(a1.w, wv.w, acc1);
        }
        sY[pA*C + o] = acc0;
        sY[pB*C + o] = acc1;
    }
    __syncthreads();

    // ---- Stage J: LayerNorm (warp wp -> point wp) + global store ----
    {
        int wp = tid >> 5, lid = tid & 31;
        float y0 = sY[wp*C + lid];
        float y1 = sY[wp*C + lid + 32];
        float s  = y0 + y1;
        float s2 = y0*y0 + y1*y1;
#pragma unroll
        for (int off = 16; off; off >>= 1) {
            s  += __shfl_xor_sync(0xFFFFFFFFu, s,  off);
            s2 += __shfl_xor_sync(0xFFFFFFFFu, s2, off);
        }
        float mu  = s * (1.f/64.f);
        float var = s2 * (1.f/64.f) - mu*mu;
        float rs  = rsqrtf(var + 1e-5f);
        int g = p0 + wp;
        out[(size_t)g*C + lid]      = (y0 - mu) * rs * lnw[lid]      + lnb[lid];
        out[(size_t)g*C + lid + 32] = (y1 - mu) * rs * lnw[lid + 32] + lnb[lid + 32];
    }
}

// ---------------- launch ----------------
extern "C" void kernel_launch(void* const* d_in, const int* in_sizes, int n_in,
                              void* d_out, int out_size) {
    (void)in_sizes; (void)n_in; (void)out_size;
    const float* cxyz  = (const float*)d_in[0];
    const float* cfeat = (const float*)d_in[1];
    const float* nxyz  = (const float*)d_in[2];
    const float* nfeat = (const float*)d_in[3];
    const float* Wq    = (const float*)d_in[4];
    const float* Wk    = (const float*)d_in[5];
    const float* Wv    = (const float*)d_in[6];
    const float* Wpe1  = (const float*)d_in[7];
    const float* Wpe2  = (const float*)d_in[8];
    const float* Wa1   = (const float*)d_in[9];
    const float* Wa2   = (const float*)d_in[10];
    const float* Wproj = (const float*)d_in[11];
    const float* lnw   = (const float*)d_in[12];
    const float* lnb   = (const float*)d_in[13];

    prep_kernel<<<16, 256>>>(Wq, Wk, Wv, Wpe1, Wpe2, Wa1, Wa2);

    size_t smem = 25408 * sizeof(float);   // 101632 B -> 2 blocks/SM
    cudaFuncSetAttribute(lab_kernel, cudaFuncAttributeMaxDynamicSharedMemorySize, (int)smem);
    lab_kernel<<<NPTS/PPB, THREADS, smem>>>(cxyz, cfeat, nxyz, nfeat, Wproj, lnw, lnb, (float*)d_out);
}